// round 8
// baseline (speedup 1.0000x reference)
#include <cuda_runtime.h>
#include <cuda_fp16.h>
#include <cstdint>

#define DIM 512
#define TMt 128
#define TNt 128
#define NKC 8                     // K chunks of 64
#define STAGE_BYTES 16384         // 128 rows x 64 halves x 2B (A or B)
#define SMEM_BYTES (6 * STAGE_BYTES)   // 3 stages x (A+B) = 98304

// fp16 operands prepared once; L2-resident S, streamed qh
__device__ __half g_Sh[DIM * DIM];                 // S = A + A^T   (512 KB)
__device__ __half g_qh[(size_t)65536 * DIM];       // q in fp16     (64 MB)

__global__ void prep_S(const float* __restrict__ A) {
    int i = blockIdx.x * 256 + threadIdx.x;        // 262144
    int e = i >> 9, d = i & 511;
    g_Sh[i] = __float2half(A[i] + A[d * DIM + e]);
}

// One pass over q: write fp16 copy (GEMM A operand) AND out[:,512:] = q (fp32).
__global__ void prep_q(const float* __restrict__ pq, float* __restrict__ out) {
    const size_t i0 = ((size_t)blockIdx.x * 256 + threadIdx.x) * 4;   // grid 8192
    #pragma unroll
    for (int t = 0; t < 4; t++) {
        const size_t i = i0 + t;
        const int b = (int)(i >> 7);
        const int dc = ((int)i & 127) * 4;
        const float4 v = *reinterpret_cast<const float4*>(pq + (size_t)b * 1024 + DIM + dc);
        __half2 h01 = __floats2half2_rn(v.x, v.y);
        __half2 h23 = __floats2half2_rn(v.z, v.w);
        uint2 packed;
        packed.x = *reinterpret_cast<uint32_t*>(&h01);
        packed.y = *reinterpret_cast<uint32_t*>(&h23);
        *reinterpret_cast<uint2*>(g_qh + (size_t)b * DIM + dc) = packed;
        *reinterpret_cast<float4*>(out + (size_t)b * 1024 + DIM + dc) = v;
    }
}

// ---------------- helpers ----------------
__device__ __forceinline__ uint32_t smem_u32(const void* p) {
    return (uint32_t)__cvta_generic_to_shared(p);
}
__device__ __forceinline__ void cpa16(uint32_t dst, const void* src) {
    asm volatile("cp.async.cg.shared.global [%0], [%1], 16;" :: "r"(dst), "l"(src) : "memory");
}
__device__ __forceinline__ void ldm4(uint32_t* r, uint32_t addr) {
    asm volatile("ldmatrix.sync.aligned.m8n8.x4.shared.b16 {%0,%1,%2,%3}, [%4];"
                 : "=r"(r[0]), "=r"(r[1]), "=r"(r[2]), "=r"(r[3]) : "r"(addr));
}
__device__ __forceinline__ void mma16816(float* d, const uint32_t* a, uint32_t b0, uint32_t b1) {
    asm volatile(
        "mma.sync.aligned.m16n8k16.row.col.f32.f16.f16.f32 "
        "{%0,%1,%2,%3}, {%4,%5,%6,%7}, {%8,%9}, {%0,%1,%2,%3};"
        : "+f"(d[0]), "+f"(d[1]), "+f"(d[2]), "+f"(d[3])
        : "r"(a[0]), "r"(a[1]), "r"(a[2]), "r"(a[3]), "r"(b0), "r"(b1));
}

// ---------------- main GEMM kernel ----------------
// out[:, 0:512] = p + q @ S   (q-copy half handled by prep_q)
__global__ void __launch_bounds__(256, 2)
gemm_fused(const float* __restrict__ pq, float* __restrict__ out) {
    extern __shared__ __align__(1024) char smem_raw[];
    const uint32_t sA = smem_u32(smem_raw);                 // 3 A stages
    const uint32_t sB = sA + 3 * STAGE_BYTES;               // 3 B stages

    const int tid = threadIdx.x;
    const int wid = tid >> 5, lane = tid & 31;
    const int wm = wid & 3, wn = wid >> 2;                  // 4(m) x 2(n); warp tile 32x64
    const int l4 = lane >> 2, lc = lane & 3;
    const int bx = blockIdx.x;
    const int m0 = (bx >> 2) * TMt;
    const int n0 = (bx & 3) * TNt;

    // ldmatrix lane-address components
    const int sw = lane & 7;                                // swizzle xor
    const int rowA = wm * 32 + (lane & 7) + ((lane >> 3) & 1) * 8;   // + mf*16
    const int hiA = (lane >> 4) & 1;
    const int rowB = wn * 64 + (lane & 7) + ((lane >> 4) & 1) * 8;   // + pair*16
    const int hiB = (lane >> 3) & 1;

    // issue cp.async for K-chunk kc into stage kc%3 (swizzled 128B rows)
    auto issue = [&](int kc) {
        const uint32_t as = sA + (kc % 3) * STAGE_BYTES;
        const uint32_t bs = sB + (kc % 3) * STAGE_BYTES;
        const __half* aq = g_qh + (size_t)m0 * DIM + kc * 64;
        const __half* ss = g_Sh + (size_t)n0 * DIM + kc * 64;
        #pragma unroll
        for (int j = 0; j < 4; j++) {                       // 1024 x 16B each
            int i = tid + j * 256;
            int r = i >> 3, c = i & 7;
            uint32_t off = r * 128 + ((c ^ (r & 7)) << 4);
            cpa16(as + off, aq + (size_t)r * DIM + c * 8);
            cpa16(bs + off, ss + (size_t)r * DIM + c * 8);
        }
        asm volatile("cp.async.commit_group;" ::: "memory");
    };

    issue(0); issue(1); issue(2);

    float d[2][8][4];
    #pragma unroll
    for (int i = 0; i < 2; i++)
        #pragma unroll
        for (int j = 0; j < 8; j++)
            #pragma unroll
            for (int k = 0; k < 4; k++) d[i][j][k] = 0.f;

    for (int kc = 0; kc < NKC; kc++) {
        asm volatile("cp.async.wait_group 2;" ::: "memory");
        __syncthreads();                                    // chunk kc visible to all

        const uint32_t as = sA + (kc % 3) * STAGE_BYTES;
        const uint32_t bs = sB + (kc % 3) * STAGE_BYTES;

        #pragma unroll
        for (int s = 0; s < 4; s++) {
            uint32_t a[2][4];
            #pragma unroll
            for (int mf = 0; mf < 2; mf++)
                ldm4(a[mf], as + (rowA + mf * 16) * 128 + (((2 * s + hiA) ^ sw) << 4));
            #pragma unroll
            for (int p = 0; p < 4; p++) {
                uint32_t b[4];
                ldm4(b, bs + (rowB + p * 16) * 128 + (((2 * s + hiB) ^ sw) << 4));
                mma16816(d[0][2 * p + 0], a[0], b[0], b[1]);
                mma16816(d[0][2 * p + 1], a[0], b[2], b[3]);
                mma16816(d[1][2 * p + 0], a[1], b[0], b[1]);
                mma16816(d[1][2 * p + 1], a[1], b[2], b[3]);
            }
        }

        __syncthreads();                                    // all warps done with stage kc%3
        if (kc + 3 < NKC) issue(kc + 3);
        else asm volatile("cp.async.commit_group;" ::: "memory");   // keep group count uniform
    }

    // ---- epilogue: out[:, n0 + c] = p + pterm
    #pragma unroll
    for (int mf = 0; mf < 2; mf++) {
        #pragma unroll
        for (int rh = 0; rh < 2; rh++) {
            int row = m0 + wm * 32 + mf * 16 + rh * 8 + l4;
            const float* pr = pq + (size_t)row * 1024 + n0 + wn * 64 + 2 * lc;
            float* orow = out + (size_t)row * 1024 + n0 + wn * 64 + 2 * lc;
            #pragma unroll
            for (int nf = 0; nf < 8; nf++) {
                float2 pv = *reinterpret_cast<const float2*>(pr + nf * 8);
                float2 ov;
                ov.x = pv.x + d[mf][nf][rh * 2 + 0];
                ov.y = pv.y + d[mf][nf][rh * 2 + 1];
                *reinterpret_cast<float2*>(orow + nf * 8) = ov;
            }
        }
    }
}

extern "C" void kernel_launch(void* const* d_in, const int* in_sizes, int n_in,
                              void* d_out, int out_size) {
    const float* pq = (const float*)d_in[0];
    const float* A  = (const float*)d_in[1];
    if (n_in >= 2 && in_sizes[0] == DIM * DIM) {   // defensive: swap if order differs
        A  = (const float*)d_in[0];
        pq = (const float*)d_in[1];
    }
    float* out = (float*)d_out;

    cudaFuncSetAttribute(gemm_fused, cudaFuncAttributeMaxDynamicSharedMemorySize, SMEM_BYTES);
    prep_S<<<(DIM * DIM) / 256, 256>>>(A);
    prep_q<<<8192, 256>>>(pq, out);
    gemm_fused<<<(65536 / TMt) * (DIM / TNt), 256, SMEM_BYTES>>>(pq, out);
}

// round 10
// speedup vs baseline: 1.1047x; 1.1047x over previous
#include <cuda_runtime.h>
#include <cuda_fp16.h>
#include <cstdint>

#define DIM 512
#define TMt 128
#define TNt 128
#define NKC 8                     // K chunks of 64
#define STAGE_BYTES 16384         // 128 rows x 64 halves x 2B (A or B)
#define SMEM_BYTES (6 * STAGE_BYTES)   // 3 stages x (A+B) = 98304

// fp16 operands prepared once; L2-resident S, streamed qh
__device__ __half g_Sh[DIM * DIM];                 // S = A + A^T   (512 KB)
__device__ __half g_qh[(size_t)65536 * DIM];       // q in fp16     (64 MB)

// Single prep kernel: blocks [0,512) build S; blocks [512, 16896) convert q
// (2 units of work per thread, both fully coalesced).
__global__ void __launch_bounds__(256) prep_all(const float* __restrict__ pq,
                                                const float* __restrict__ A) {
    const int b = blockIdx.x;
    if (b < 512) {
        int i0 = b * 512 + threadIdx.x;            // 262144 S elements, 2 per thread
        #pragma unroll
        for (int t = 0; t < 2; t++) {
            int i = i0 + t * 256;
            int e = i >> 9, dd = i & 511;
            g_Sh[i] = __float2half(A[i] + A[dd * DIM + e]);
        }
    } else {
        size_t i0 = (size_t)(b - 512) * 512 + threadIdx.x;   // 8388608 float4s, 2 per thread
        #pragma unroll
        for (int t = 0; t < 2; t++) {
            size_t i = i0 + t * 256;
            int row = (int)(i >> 7), dc = ((int)i & 127) * 4;
            float4 v = *reinterpret_cast<const float4*>(pq + (size_t)row * 1024 + DIM + dc);
            __half2 h01 = __floats2half2_rn(v.x, v.y);
            __half2 h23 = __floats2half2_rn(v.z, v.w);
            uint2 packed;
            packed.x = *reinterpret_cast<uint32_t*>(&h01);
            packed.y = *reinterpret_cast<uint32_t*>(&h23);
            *reinterpret_cast<uint2*>(g_qh + (size_t)row * DIM + dc) = packed;
        }
    }
}

// ---------------- helpers ----------------
__device__ __forceinline__ uint32_t smem_u32(const void* p) {
    return (uint32_t)__cvta_generic_to_shared(p);
}
__device__ __forceinline__ void cpa16(uint32_t dst, const void* src) {
    asm volatile("cp.async.cg.shared.global [%0], [%1], 16;" :: "r"(dst), "l"(src) : "memory");
}
__device__ __forceinline__ void ldm4(uint32_t* r, uint32_t addr) {
    asm volatile("ldmatrix.sync.aligned.m8n8.x4.shared.b16 {%0,%1,%2,%3}, [%4];"
                 : "=r"(r[0]), "=r"(r[1]), "=r"(r[2]), "=r"(r[3]) : "r"(addr));
}
__device__ __forceinline__ void mma16816(float* d, const uint32_t* a, uint32_t b0, uint32_t b1) {
    asm volatile(
        "mma.sync.aligned.m16n8k16.row.col.f32.f16.f16.f32 "
        "{%0,%1,%2,%3}, {%4,%5,%6,%7}, {%8,%9}, {%0,%1,%2,%3};"
        : "+f"(d[0]), "+f"(d[1]), "+f"(d[2]), "+f"(d[3])
        : "r"(a[0]), "r"(a[1]), "r"(a[2]), "r"(a[3]), "r"(b0), "r"(b1));
}

// ---------------- main fused kernel ----------------
// out[:, 0:512]    = p + q @ S
// out[:, 512:1024] = q   (exact fp32 passthrough, streamed in mainloop)
__global__ void __launch_bounds__(256, 2)
gemm_fused(const float* __restrict__ pq, float* __restrict__ out) {
    extern __shared__ __align__(1024) char smem_raw[];
    const uint32_t sA = smem_u32(smem_raw);                 // 3 A stages
    const uint32_t sB = sA + 3 * STAGE_BYTES;               // 3 B stages

    const int tid = threadIdx.x;
    const int wid = tid >> 5, lane = tid & 31;
    const int wm = wid & 3, wn = wid >> 2;                  // 4(m) x 2(n); warp tile 32x64
    const int l4 = lane >> 2, lc = lane & 3;
    const int bx = blockIdx.x;
    const int m0 = (bx >> 2) * TMt;
    const int n0 = (bx & 3) * TNt;

    // ldmatrix lane-address components
    const int sw = lane & 7;                                // swizzle xor
    const int rowA = wm * 32 + (lane & 7) + ((lane >> 3) & 1) * 8;   // + mf*16
    const int hiA = (lane >> 4) & 1;
    const int rowB = wn * 64 + (lane & 7) + ((lane >> 4) & 1) * 8;   // + pair*16
    const int hiB = (lane >> 3) & 1;

    // issue cp.async for K-chunk kc into stage kc%3 (swizzled 128B rows)
    auto issue = [&](int kc) {
        const uint32_t as = sA + (kc % 3) * STAGE_BYTES;
        const uint32_t bs = sB + (kc % 3) * STAGE_BYTES;
        const __half* aq = g_qh + (size_t)m0 * DIM + kc * 64;
        const __half* ss = g_Sh + (size_t)n0 * DIM + kc * 64;
        #pragma unroll
        for (int j = 0; j < 4; j++) {                       // 1024 x 16B each
            int i = tid + j * 256;
            int r = i >> 3, c = i & 7;
            uint32_t off = r * 128 + ((c ^ (r & 7)) << 4);
            cpa16(as + off, aq + (size_t)r * DIM + c * 8);
            cpa16(bs + off, ss + (size_t)r * DIM + c * 8);
        }
        asm volatile("cp.async.commit_group;" ::: "memory");
    };

    issue(0); issue(1); issue(2);

    float d[2][8][4];
    #pragma unroll
    for (int i = 0; i < 2; i++)
        #pragma unroll
        for (int j = 0; j < 8; j++)
            #pragma unroll
            for (int k = 0; k < 4; k++) d[i][j][k] = 0.f;

    for (int kc = 0; kc < NKC; kc++) {
        asm volatile("cp.async.wait_group 2;" ::: "memory");
        __syncthreads();                                    // chunk kc visible to all

        const uint32_t as = sA + (kc % 3) * STAGE_BYTES;
        const uint32_t bs = sB + (kc % 3) * STAGE_BYTES;

        // q-copy slice: 512 float4s per chunk (2 per thread), pure fp32 passthrough
        {
            int i = tid + kc * 512;
            #pragma unroll
            for (int t = 0; t < 2; t++, i += 256) {
                int r = i >> 5, c = i & 31;
                const float* qs = pq + (size_t)(m0 + r) * 1024 + DIM + n0 + c * 4;
                float* qo = out + (size_t)(m0 + r) * 1024 + DIM + n0 + c * 4;
                *reinterpret_cast<float4*>(qo) = *reinterpret_cast<const float4*>(qs);
            }
        }

        #pragma unroll
        for (int s = 0; s < 4; s++) {
            uint32_t a[2][4];
            #pragma unroll
            for (int mf = 0; mf < 2; mf++)
                ldm4(a[mf], as + (rowA + mf * 16) * 128 + (((2 * s + hiA) ^ sw) << 4));
            #pragma unroll
            for (int p = 0; p < 4; p++) {
                uint32_t b[4];
                ldm4(b, bs + (rowB + p * 16) * 128 + (((2 * s + hiB) ^ sw) << 4));
                mma16816(d[0][2 * p + 0], a[0], b[0], b[1]);
                mma16816(d[0][2 * p + 1], a[0], b[2], b[3]);
                mma16816(d[1][2 * p + 0], a[1], b[0], b[1]);
                mma16816(d[1][2 * p + 1], a[1], b[2], b[3]);
            }
        }

        __syncthreads();                                    // all warps done with stage kc%3
        if (kc + 3 < NKC) issue(kc + 3);
        else asm volatile("cp.async.commit_group;" ::: "memory");   // keep group count uniform
    }

    // ---- epilogue: out[:, n0 + c] = p + pterm
    #pragma unroll
    for (int mf = 0; mf < 2; mf++) {
        #pragma unroll
        for (int rh = 0; rh < 2; rh++) {
            int row = m0 + wm * 32 + mf * 16 + rh * 8 + l4;
            const float* pr = pq + (size_t)row * 1024 + n0 + wn * 64 + 2 * lc;
            float* orow = out + (size_t)row * 1024 + n0 + wn * 64 + 2 * lc;
            #pragma unroll
            for (int nf = 0; nf < 8; nf++) {
                float2 pv = *reinterpret_cast<const float2*>(pr + nf * 8);
                float2 ov;
                ov.x = pv.x + d[mf][nf][rh * 2 + 0];
                ov.y = pv.y + d[mf][nf][rh * 2 + 1];
                *reinterpret_cast<float2*>(orow + nf * 8) = ov;
            }
        }
    }
}

extern "C" void kernel_launch(void* const* d_in, const int* in_sizes, int n_in,
                              void* d_out, int out_size) {
    const float* pq = (const float*)d_in[0];
    const float* A  = (const float*)d_in[1];
    if (n_in >= 2 && in_sizes[0] == DIM * DIM) {   // defensive: swap if order differs
        A  = (const float*)d_in[0];
        pq = (const float*)d_in[1];
    }
    float* out = (float*)d_out;

    cudaFuncSetAttribute(gemm_fused, cudaFuncAttributeMaxDynamicSharedMemorySize, SMEM_BYTES);
    prep_all<<<16896, 256>>>(pq, A);
    gemm_fused<<<(65536 / TMt) * (DIM / TNt), 256, SMEM_BYTES>>>(pq, out);
}

// round 11
// speedup vs baseline: 1.2325x; 1.1157x over previous
#include <cuda_runtime.h>
#include <cuda_fp16.h>
#include <cstdint>

#define DIM 512
#define TMt 128
#define TNt 128
#define NKC 8                     // K chunks of 64
#define STAGE_BYTES 16384         // 128 rows x 64 halves x 2B (A or B)
#define SMEM_BYTES (6 * STAGE_BYTES)   // 3 stages x (A+B) = 98304

// fp16 operands prepared once; L2-resident S, streamed qh
__device__ __half g_Sh[DIM * DIM];                 // S = A + A^T   (512 KB)
__device__ __half g_qh[(size_t)65536 * DIM];       // q in fp16     (64 MB)

// Single prep kernel: blocks [0,512) build S; blocks [512, 16896) convert q
// (2 units of work per thread, both fully coalesced).
__global__ void __launch_bounds__(256) prep_all(const float* __restrict__ pq,
                                                const float* __restrict__ A) {
    const int b = blockIdx.x;
    if (b < 512) {
        int i0 = b * 512 + threadIdx.x;            // 262144 S elements, 2 per thread
        #pragma unroll
        for (int t = 0; t < 2; t++) {
            int i = i0 + t * 256;
            int e = i >> 9, dd = i & 511;
            g_Sh[i] = __float2half(A[i] + A[dd * DIM + e]);
        }
    } else {
        size_t i0 = (size_t)(b - 512) * 512 + threadIdx.x;   // 8388608 float4s, 2 per thread
        #pragma unroll
        for (int t = 0; t < 2; t++) {
            size_t i = i0 + t * 256;
            int row = (int)(i >> 7), dc = ((int)i & 127) * 4;
            float4 v = *reinterpret_cast<const float4*>(pq + (size_t)row * 1024 + DIM + dc);
            __half2 h01 = __floats2half2_rn(v.x, v.y);
            __half2 h23 = __floats2half2_rn(v.z, v.w);
            uint2 packed;
            packed.x = *reinterpret_cast<uint32_t*>(&h01);
            packed.y = *reinterpret_cast<uint32_t*>(&h23);
            *reinterpret_cast<uint2*>(g_qh + (size_t)row * DIM + dc) = packed;
        }
    }
}

// ---------------- helpers ----------------
__device__ __forceinline__ uint32_t smem_u32(const void* p) {
    return (uint32_t)__cvta_generic_to_shared(p);
}
__device__ __forceinline__ void cpa16(uint32_t dst, const void* src) {
    asm volatile("cp.async.cg.shared.global [%0], [%1], 16;" :: "r"(dst), "l"(src) : "memory");
}
__device__ __forceinline__ void ldm4(uint32_t* r, uint32_t addr) {
    asm volatile("ldmatrix.sync.aligned.m8n8.x4.shared.b16 {%0,%1,%2,%3}, [%4];"
                 : "=r"(r[0]), "=r"(r[1]), "=r"(r[2]), "=r"(r[3]) : "r"(addr));
}
__device__ __forceinline__ void mma16816(float* d, const uint32_t* a, uint32_t b0, uint32_t b1) {
    asm volatile(
        "mma.sync.aligned.m16n8k16.row.col.f32.f16.f16.f32 "
        "{%0,%1,%2,%3}, {%4,%5,%6,%7}, {%8,%9}, {%0,%1,%2,%3};"
        : "+f"(d[0]), "+f"(d[1]), "+f"(d[2]), "+f"(d[3])
        : "r"(a[0]), "r"(a[1]), "r"(a[2]), "r"(a[3]), "r"(b0), "r"(b1));
}

// ---------------- main fused kernel ----------------
// out[:, 0:512]    = p + q @ S
// out[:, 512:1024] = q   (exact fp32 passthrough, pipelined through the mainloop)
__global__ void __launch_bounds__(256, 2)
gemm_fused(const float* __restrict__ pq, float* __restrict__ out) {
    extern __shared__ __align__(1024) char smem_raw[];
    const uint32_t sA = smem_u32(smem_raw);                 // 3 A stages
    const uint32_t sB = sA + 3 * STAGE_BYTES;               // 3 B stages

    const int tid = threadIdx.x;
    const int wid = tid >> 5, lane = tid & 31;
    const int wm = wid & 3, wn = wid >> 2;                  // 4(m) x 2(n); warp tile 32x64
    const int l4 = lane >> 2, lc = lane & 3;
    const int bx = blockIdx.x;
    const int m0 = (bx >> 2) * TMt;
    const int n0 = (bx & 3) * TNt;

    // ldmatrix lane-address components
    const int sw = lane & 7;                                // swizzle xor
    const int rowA = wm * 32 + (lane & 7) + ((lane >> 3) & 1) * 8;   // + mf*16
    const int hiA = (lane >> 4) & 1;
    const int rowB = wn * 64 + (lane & 7) + ((lane >> 4) & 1) * 8;   // + pair*16
    const int hiB = (lane >> 3) & 1;

    // issue cp.async for K-chunk kc into stage kc%3 (swizzled 128B rows)
    auto issue = [&](int kc) {
        const uint32_t as = sA + (kc % 3) * STAGE_BYTES;
        const uint32_t bs = sB + (kc % 3) * STAGE_BYTES;
        const __half* aq = g_qh + (size_t)m0 * DIM + kc * 64;
        const __half* ss = g_Sh + (size_t)n0 * DIM + kc * 64;
        #pragma unroll
        for (int j = 0; j < 4; j++) {                       // 1024 x 16B each
            int i = tid + j * 256;
            int r = i >> 3, c = i & 7;
            uint32_t off = r * 128 + ((c ^ (r & 7)) << 4);
            cpa16(as + off, aq + (size_t)r * DIM + c * 8);
            cpa16(bs + off, ss + (size_t)r * DIM + c * 8);
        }
        asm volatile("cp.async.commit_group;" ::: "memory");
    };

    // q-copy slice addressing: slice kc covers 512 float4s, 2 per thread
    auto qsrc = [&](int kc, int t) -> const float* {
        int i = tid + kc * 512 + t * 256;
        int r = i >> 5, c = i & 31;
        return pq + (size_t)(m0 + r) * 1024 + DIM + n0 + c * 4;
    };
    auto qdst = [&](int kc, int t) -> float* {
        int i = tid + kc * 512 + t * 256;
        int r = i >> 5, c = i & 31;
        return out + (size_t)(m0 + r) * 1024 + DIM + n0 + c * 4;
    };

    issue(0); issue(1);

    float4 qv[2];                                           // prefetched q-copy slice
    qv[0] = *reinterpret_cast<const float4*>(qsrc(0, 0));
    qv[1] = *reinterpret_cast<const float4*>(qsrc(0, 1));

    float d[2][8][4];
    #pragma unroll
    for (int i = 0; i < 2; i++)
        #pragma unroll
        for (int j = 0; j < 8; j++)
            #pragma unroll
            for (int k = 0; k < 4; k++) d[i][j][k] = 0.f;

    for (int kc = 0; kc < NKC; kc++) {
        asm volatile("cp.async.wait_group 1;" ::: "memory");   // chunk kc landed
        __syncthreads();                                       // single barrier per iter

        // refill stage (kc+2)%3 == (kc-1)%3 (reads finished before the sync above)
        if (kc + 2 < NKC) issue(kc + 2);
        else asm volatile("cp.async.commit_group;" ::: "memory");

        // q-copy: store prefetched slice kc, prefetch slice kc+1 (hides under MMA)
        *reinterpret_cast<float4*>(qdst(kc, 0)) = qv[0];
        *reinterpret_cast<float4*>(qdst(kc, 1)) = qv[1];
        if (kc + 1 < NKC) {
            qv[0] = *reinterpret_cast<const float4*>(qsrc(kc + 1, 0));
            qv[1] = *reinterpret_cast<const float4*>(qsrc(kc + 1, 1));
        }

        const uint32_t as = sA + (kc % 3) * STAGE_BYTES;
        const uint32_t bs = sB + (kc % 3) * STAGE_BYTES;

        #pragma unroll
        for (int s = 0; s < 4; s++) {
            uint32_t a[2][4];
            #pragma unroll
            for (int mf = 0; mf < 2; mf++)
                ldm4(a[mf], as + (rowA + mf * 16) * 128 + (((2 * s + hiA) ^ sw) << 4));
            #pragma unroll
            for (int p = 0; p < 4; p++) {
                uint32_t b[4];
                ldm4(b, bs + (rowB + p * 16) * 128 + (((2 * s + hiB) ^ sw) << 4));
                mma16816(d[0][2 * p + 0], a[0], b[0], b[1]);
                mma16816(d[0][2 * p + 1], a[0], b[2], b[3]);
                mma16816(d[1][2 * p + 0], a[1], b[0], b[1]);
                mma16816(d[1][2 * p + 1], a[1], b[2], b[3]);
            }
        }
    }

    // ---- epilogue: out[:, n0 + c] = p + pterm
    #pragma unroll
    for (int mf = 0; mf < 2; mf++) {
        #pragma unroll
        for (int rh = 0; rh < 2; rh++) {
            int row = m0 + wm * 32 + mf * 16 + rh * 8 + l4;
            const float* pr = pq + (size_t)row * 1024 + n0 + wn * 64 + 2 * lc;
            float* orow = out + (size_t)row * 1024 + n0 + wn * 64 + 2 * lc;
            #pragma unroll
            for (int nf = 0; nf < 8; nf++) {
                float2 pv = *reinterpret_cast<const float2*>(pr + nf * 8);
                float2 ov;
                ov.x = pv.x + d[mf][nf][rh * 2 + 0];
                ov.y = pv.y + d[mf][nf][rh * 2 + 1];
                *reinterpret_cast<float2*>(orow + nf * 8) = ov;
            }
        }
    }
}

extern "C" void kernel_launch(void* const* d_in, const int* in_sizes, int n_in,
                              void* d_out, int out_size) {
    const float* pq = (const float*)d_in[0];
    const float* A  = (const float*)d_in[1];
    if (n_in >= 2 && in_sizes[0] == DIM * DIM) {   // defensive: swap if order differs
        A  = (const float*)d_in[0];
        pq = (const float*)d_in[1];
    }
    float* out = (float*)d_out;

    cudaFuncSetAttribute(gemm_fused, cudaFuncAttributeMaxDynamicSharedMemorySize, SMEM_BYTES);
    prep_all<<<16896, 256>>>(pq, A);
    gemm_fused<<<(65536 / TMt) * (DIM / TNt), 256, SMEM_BYTES>>>(pq, out);
}